// round 2
// baseline (speedup 1.0000x reference)
#include <cuda_runtime.h>
#include <cstddef>

#define P_C     16
#define K_C     256
#define W_C     8
#define F_IN_C  128
#define F_OUT_C 128
#define N_SRC_MAX 200000
#define N_DST_MAX 100000

// Scratch (allocation-free rule: __device__ globals)
__device__ float g_feat[(size_t)N_SRC_MAX * F_IN_C];     // decoded per-source features
__device__ float g_hneigh[(size_t)N_DST_MAX * F_IN_C];   // mean-aggregated neighbor features

// ---------------------------------------------------------------------------
// Kernel 1: decode feat[s, p*8+w] = codebook[p, codes[s,p], w]
// 32 threads per source, each lane writes one float4 (4 features).
// ---------------------------------------------------------------------------
__global__ void decode_kernel(const int* __restrict__ codes,
                              const float* __restrict__ codebook,
                              int n_src) {
    int gid = blockIdx.x * blockDim.x + threadIdx.x;
    int s = gid >> 5;
    if (s >= n_src) return;
    int l = gid & 31;
    int p  = l >> 1;            // feature f = l*4.. -> p = f/8 = l/2
    int w4 = (l & 1) << 2;      // w base = (f%8) chunk
    int code = __ldg(codes + s * P_C + p);
    float4 v = *reinterpret_cast<const float4*>(
        codebook + ((size_t)((p << 8) + code)) * W_C + w4);
    *reinterpret_cast<float4*>(g_feat + (size_t)s * F_IN_C + (l << 2)) = v;
}

// ---------------------------------------------------------------------------
// Kernel 2: gather + mean. One warp per destination.
// Lane l accumulates features [4l, 4l+4). Indices preloaded + shfl-broadcast.
// ---------------------------------------------------------------------------
__global__ void gather_kernel(const int* __restrict__ indices,
                              const int* __restrict__ indptr,
                              int n_dst) {
    int warp = (blockIdx.x * blockDim.x + threadIdx.x) >> 5;
    int lane = threadIdx.x & 31;
    if (warp >= n_dst) return;

    int start = __ldg(indptr + warp);
    int end   = __ldg(indptr + warp + 1);
    int deg   = end - start;

    float4 acc = make_float4(0.f, 0.f, 0.f, 0.f);
    int my_idx = (lane < deg) ? __ldg(indices + start + lane) : 0;

    if (deg == 16) {
#pragma unroll
        for (int e = 0; e < 16; e++) {
            int src = __shfl_sync(0xffffffffu, my_idx, e);
            float4 v = *reinterpret_cast<const float4*>(
                g_feat + (size_t)src * F_IN_C + (lane << 2));
            acc.x += v.x; acc.y += v.y; acc.z += v.z; acc.w += v.w;
        }
    } else {
        for (int e = 0; e < deg; e++) {
            int src = (e < 32) ? __shfl_sync(0xffffffffu, my_idx, e)
                               : __ldg(indices + start + e);
            float4 v = *reinterpret_cast<const float4*>(
                g_feat + (size_t)src * F_IN_C + (lane << 2));
            acc.x += v.x; acc.y += v.y; acc.z += v.z; acc.w += v.w;
        }
    }
    float s = 1.0f / fmaxf((float)deg, 1.0f);
    acc.x *= s; acc.y *= s; acc.z *= s; acc.w *= s;
    *reinterpret_cast<float4*>(g_hneigh + (size_t)warp * F_IN_C + (lane << 2)) = acc;
}

// ---------------------------------------------------------------------------
// Kernel 3: out = h_neigh @ Wn.T + h_self @ Ws.T + b
// M x 128 GEMM with K=256 (concatenated). 128x128 CTA tile, 8x8 register tile
// per thread (256 threads), k-major smem, double buffered.
// Inner product uses packed fma.rn.f32x2 (FFMA2): 2 fp32 FMAs / instruction,
// 2x the fp32 fma-pipe throughput vs scalar FFMA (PTX-only pattern).
// ---------------------------------------------------------------------------
#define MT 128
#define KT 16

__device__ __forceinline__ void load_A_tile(float dst[KT][MT],
                                            const float* __restrict__ src,
                                            int m0, int kk, int tid, int n_dst) {
#pragma unroll
    for (int i = 0; i < 2; i++) {
        int f4  = tid + (i << 8);
        int row = f4 >> 2;
        int c   = f4 & 3;
        int gr  = m0 + row;
        if (gr > n_dst - 1) gr = n_dst - 1;
        float4 v = *reinterpret_cast<const float4*>(
            src + (size_t)gr * F_IN_C + kk + (c << 2));
        dst[(c << 2) + 0][row] = v.x;
        dst[(c << 2) + 1][row] = v.y;
        dst[(c << 2) + 2][row] = v.z;
        dst[(c << 2) + 3][row] = v.w;
    }
}

__device__ __forceinline__ void load_B_tile(float dst[KT][128],
                                            const float* __restrict__ src,
                                            int kk, int tid) {
#pragma unroll
    for (int i = 0; i < 2; i++) {
        int f4  = tid + (i << 8);
        int row = f4 >> 2;
        int c   = f4 & 3;
        float4 v = *reinterpret_cast<const float4*>(
            src + (size_t)row * F_IN_C + kk + (c << 2));
        dst[(c << 2) + 0][row] = v.x;
        dst[(c << 2) + 1][row] = v.y;
        dst[(c << 2) + 2][row] = v.z;
        dst[(c << 2) + 3][row] = v.w;
    }
}

__global__ __launch_bounds__(256, 2) void gemm_kernel(
    const float* __restrict__ hself,
    const float* __restrict__ Wn,
    const float* __restrict__ Ws,
    const float* __restrict__ bias,
    float* __restrict__ out,
    int n_dst) {
    __shared__ float As[2][KT][MT];
    __shared__ float Bs[2][KT][128];

    int tid = threadIdx.x;
    int tx  = tid & 15;   // n-group (8 cols = 4 f32x2 pairs)
    int ty  = tid >> 4;   // m-group (8 rows)
    int m0  = blockIdx.x * MT;

    // acc64[i][j] holds output pair (col 2j: lo 32 bits, col 2j+1: hi 32 bits)
    unsigned long long acc64[8][4];
#pragma unroll
    for (int i = 0; i < 8; i++)
#pragma unroll
        for (int j = 0; j < 4; j++) acc64[i][j] = 0ull;

    // prologue: tile 0 (k in [0,16) -> neighbor half)
    load_A_tile(As[0], g_hneigh, m0, 0, tid, n_dst);
    load_B_tile(Bs[0], Wn, 0, tid);
    __syncthreads();

    const int NTILES = 256 / KT;  // 16
    for (int t = 0; t < NTILES; t++) {
        int cur = t & 1;
        int nxt = cur ^ 1;
        if (t + 1 < NTILES) {
            int kt = (t + 1) * KT;
            const float* Asrc = (kt < 128) ? (const float*)g_hneigh : hself;
            const float* Bsrc = (kt < 128) ? Wn : Ws;
            int kk = kt & 127;
            load_A_tile(As[nxt], Asrc, m0, kk, tid, n_dst);
            load_B_tile(Bs[nxt], Bsrc, kk, tid);
        }
#pragma unroll
        for (int k = 0; k < KT; k++) {
            float4 a0 = *reinterpret_cast<const float4*>(&As[cur][k][ty * 8]);
            float4 a1 = *reinterpret_cast<const float4*>(&As[cur][k][ty * 8 + 4]);
            float4 b0 = *reinterpret_cast<const float4*>(&Bs[cur][k][tx * 8]);
            float4 b1 = *reinterpret_cast<const float4*>(&Bs[cur][k][tx * 8 + 4]);

            float a[8] = {a0.x, a0.y, a0.z, a0.w, a1.x, a1.y, a1.z, a1.w};
            unsigned long long av[8];
#pragma unroll
            for (int i = 0; i < 8; i++)
                asm("mov.b64 %0, {%1, %1};" : "=l"(av[i]) : "f"(a[i]));

            unsigned long long bv[4];
            asm("mov.b64 %0, {%1, %2};" : "=l"(bv[0]) : "f"(b0.x), "f"(b0.y));
            asm("mov.b64 %0, {%1, %2};" : "=l"(bv[1]) : "f"(b0.z), "f"(b0.w));
            asm("mov.b64 %0, {%1, %2};" : "=l"(bv[2]) : "f"(b1.x), "f"(b1.y));
            asm("mov.b64 %0, {%1, %2};" : "=l"(bv[3]) : "f"(b1.z), "f"(b1.w));

#pragma unroll
            for (int i = 0; i < 8; i++)
#pragma unroll
                for (int j = 0; j < 4; j++)
                    asm("fma.rn.f32x2 %0, %1, %2, %0;"
                        : "+l"(acc64[i][j]) : "l"(av[i]), "l"(bv[j]));
        }
        __syncthreads();
    }

    // epilogue: + bias, store
    float bj[8];
#pragma unroll
    for (int j = 0; j < 8; j++) bj[j] = __ldg(bias + tx * 8 + j);

#pragma unroll
    for (int i = 0; i < 8; i++) {
        int gr = m0 + ty * 8 + i;
        if (gr < n_dst) {
            float2 p0 = *reinterpret_cast<float2*>(&acc64[i][0]);
            float2 p1 = *reinterpret_cast<float2*>(&acc64[i][1]);
            float2 p2 = *reinterpret_cast<float2*>(&acc64[i][2]);
            float2 p3 = *reinterpret_cast<float2*>(&acc64[i][3]);
            float4 o0 = make_float4(p0.x + bj[0], p0.y + bj[1],
                                    p1.x + bj[2], p1.y + bj[3]);
            float4 o1 = make_float4(p2.x + bj[4], p2.y + bj[5],
                                    p3.x + bj[6], p3.y + bj[7]);
            *reinterpret_cast<float4*>(out + (size_t)gr * F_OUT_C + tx * 8)     = o0;
            *reinterpret_cast<float4*>(out + (size_t)gr * F_OUT_C + tx * 8 + 4) = o1;
        }
    }
}

// ---------------------------------------------------------------------------
// Launch
// ---------------------------------------------------------------------------
extern "C" void kernel_launch(void* const* d_in, const int* in_sizes, int n_in,
                              void* d_out, int out_size) {
    const int*   codes    = (const int*)d_in[0];
    const int*   indices  = (const int*)d_in[1];
    const int*   indptr   = (const int*)d_in[2];
    const float* h_self   = (const float*)d_in[3];
    const float* codebook = (const float*)d_in[4];
    const float* Wn       = (const float*)d_in[5];
    const float* Ws       = (const float*)d_in[6];
    const float* b_self   = (const float*)d_in[7];
    float* out = (float*)d_out;

    int n_src = in_sizes[0] / P_C;
    int n_dst = in_sizes[2] - 1;

    // K1: decode (32 threads per source)
    {
        int total = n_src * 32;
        decode_kernel<<<(total + 255) / 256, 256>>>(codes, codebook, n_src);
    }
    // K2: gather+mean (one warp per dst)
    {
        int total = n_dst * 32;
        gather_kernel<<<(total + 255) / 256, 256>>>(indices, indptr, n_dst);
    }
    // K3: fused dual GEMM + bias (f32x2 packed FFMA)
    {
        int blocks = (n_dst + MT - 1) / MT;
        gemm_kernel<<<blocks, 256>>>(h_self, Wn, Ws, b_self, out, n_dst);
    }
}

// round 5
// speedup vs baseline: 1.6582x; 1.6582x over previous
#include <cuda_runtime.h>
#include <cstdint>
#include <cstddef>

#define P_C     16
#define W_C     8
#define F_IN_C  128
#define F_OUT_C 128
#define N_SRC_MAX 200000
#define N_DST_MAX 100000

__device__ float g_feat[(size_t)N_SRC_MAX * F_IN_C];
__device__ float g_hneigh[(size_t)N_DST_MAX * F_IN_C];

// ---------------------------------------------------------------------------
// Kernel 1: decode feat[s, p*8+w] = codebook[p, codes[s,p], w]
// ---------------------------------------------------------------------------
__global__ void decode_kernel(const int* __restrict__ codes,
                              const float* __restrict__ codebook,
                              int n_src) {
    int gid = blockIdx.x * blockDim.x + threadIdx.x;
    int s = gid >> 5;
    if (s >= n_src) return;
    int l = gid & 31;
    int p  = l >> 1;
    int w4 = (l & 1) << 2;
    int code = __ldg(codes + s * P_C + p);
    float4 v = *reinterpret_cast<const float4*>(
        codebook + ((size_t)((p << 8) + code)) * W_C + w4);
    *reinterpret_cast<float4*>(g_feat + (size_t)s * F_IN_C + (l << 2)) = v;
}

// ---------------------------------------------------------------------------
// Kernel 2: gather + mean. One warp per destination.
// ---------------------------------------------------------------------------
__global__ void gather_kernel(const int* __restrict__ indices,
                              const int* __restrict__ indptr,
                              int n_dst) {
    int warp = (blockIdx.x * blockDim.x + threadIdx.x) >> 5;
    int lane = threadIdx.x & 31;
    if (warp >= n_dst) return;

    int start = __ldg(indptr + warp);
    int end   = __ldg(indptr + warp + 1);
    int deg   = end - start;

    float4 acc = make_float4(0.f, 0.f, 0.f, 0.f);
    int my_idx = (lane < deg) ? __ldg(indices + start + lane) : 0;

    if (deg == 16) {
#pragma unroll
        for (int e = 0; e < 16; e++) {
            int src = __shfl_sync(0xffffffffu, my_idx, e);
            float4 v = *reinterpret_cast<const float4*>(
                g_feat + (size_t)src * F_IN_C + (lane << 2));
            acc.x += v.x; acc.y += v.y; acc.z += v.z; acc.w += v.w;
        }
    } else {
        for (int e = 0; e < deg; e++) {
            int src = (e < 32) ? __shfl_sync(0xffffffffu, my_idx, e)
                               : __ldg(indices + start + e);
            float4 v = *reinterpret_cast<const float4*>(
                g_feat + (size_t)src * F_IN_C + (lane << 2));
            acc.x += v.x; acc.y += v.y; acc.z += v.z; acc.w += v.w;
        }
    }
    float s = 1.0f / fmaxf((float)deg, 1.0f);
    acc.x *= s; acc.y *= s; acc.z *= s; acc.w *= s;
    *reinterpret_cast<float4*>(g_hneigh + (size_t)warp * F_IN_C + (lane << 2)) = acc;
}

// ---------------------------------------------------------------------------
// Kernel 3: tf32 mma.sync GEMM.
//   out[M,128] = [h_neigh | h_self] (M x 256) @ [Wn | Ws]^T (256 x 128) + bias
// CTA: 256 thr (8 warps), tile 128(M) x 128(N) x 256(K).
// B (128x256) fully smem-resident in fragment-permuted tf32 layout.
// A staged per 64-wide K chunk in fragment-permuted layout.
// Warp tile 32(M) x 64(N): 2 m-frags x 8 n-frags of m16n8k8.
// ---------------------------------------------------------------------------
__device__ __forceinline__ uint32_t f2tf32(float x) {
    uint32_t r;
    asm("cvt.rna.tf32.f32 %0, %1;" : "=r"(r) : "f"(x));
    return r;
}
__device__ __forceinline__ uint32_t smem_u32(const void* p) {
    uint32_t a;
    asm("{ .reg .u64 t; cvta.to.shared.u64 t, %1; cvt.u32.u64 %0, t; }"
        : "=r"(a) : "l"(p));
    return a;
}
__device__ __forceinline__ void sts32(uint32_t addr, uint32_t v) {
    asm volatile("st.shared.b32 [%0], %1;" :: "r"(addr), "r"(v) : "memory");
}
__device__ __forceinline__ void lds128(uint32_t* r, uint32_t addr) {
    asm volatile("ld.shared.v4.b32 {%0,%1,%2,%3}, [%4];"
                 : "=r"(r[0]), "=r"(r[1]), "=r"(r[2]), "=r"(r[3]) : "r"(addr));
}
__device__ __forceinline__ void lds64(uint32_t* r, uint32_t addr) {
    asm volatile("ld.shared.v2.b32 {%0,%1}, [%2];"
                 : "=r"(r[0]), "=r"(r[1]) : "r"(addr));
}
__device__ __forceinline__ void mma_tf32(float* d, const uint32_t* a, const uint32_t* b) {
    asm volatile(
        "mma.sync.aligned.m16n8k8.row.col.f32.tf32.tf32.f32 "
        "{%0,%1,%2,%3}, {%4,%5,%6,%7}, {%8,%9}, {%0,%1,%2,%3};"
        : "+f"(d[0]), "+f"(d[1]), "+f"(d[2]), "+f"(d[3])
        : "r"(a[0]), "r"(a[1]), "r"(a[2]), "r"(a[3]), "r"(b[0]), "r"(b[1]));
}

// Smem layout (bytes, dynamic):
//   B_perm: 16 nblocks x 32 ksteps x (32 lanes x 2 + 2 pad) floats = 135168 B
//   A_perm: 8 mblocks x 8 ksteps x (32 lanes x 4 + 4 pad) floats  = 33792 B
#define BGRP   66                         // floats per (nblock,kstep) group
#define AGRP   132                        // floats per (mblock,kstep) group
#define SM_B   0
#define SM_A   (16 * 32 * BGRP * 4)       // 135168
#define SM_TOT (SM_A + 8 * 8 * AGRP * 4)  // 168960

__global__ __launch_bounds__(256, 1) void gemm_mma_kernel(
    const float* __restrict__ hself,
    const float* __restrict__ Wn,
    const float* __restrict__ Ws,
    const float* __restrict__ bias,
    float* __restrict__ out,
    int n_dst) {
    extern __shared__ char smem[];
    uint32_t sb = smem_u32(smem);
    int tid  = threadIdx.x;
    int wid  = tid >> 5;
    int lane = tid & 31;
    int m0   = blockIdx.x * 128;
    int wm   = wid & 3;    // warp m index: rows wm*32 .. +31
    int wn   = wid >> 2;   // warp n index: cols wn*64 .. +63

    // ---- stage B (128 x 256) -> permuted tf32 fragments ----
#pragma unroll
    for (int i = 0; i < 32; i++) {
        int f  = i * 256 + tid;         // 8192 float4
        int n  = f >> 6;                // output col 0..127
        int kb = (f & 63) << 2;         // k base 0..252
        const float* src = (kb < 128) ? (Wn + n * 128 + kb)
                                      : (Ws + n * 128 + (kb - 128));
        float4 v = *reinterpret_cast<const float4*>(src);
        int nblock = n >> 3, n8 = n & 7;
        int kstep  = kb >> 3;
        int reg    = (kb >> 2) & 1;
        uint32_t base = sb + SM_B + (uint32_t)((nblock * 32 + kstep) * BGRP) * 4u;
        uint32_t va[4] = { f2tf32(v.x), f2tf32(v.y), f2tf32(v.z), f2tf32(v.w) };
#pragma unroll
        for (int e = 0; e < 4; e++) {
            int l = (n8 << 2) | e;
            sts32(base + (uint32_t)(l * 2 + reg) * 4u, va[e]);
        }
    }

    float acc[2][8][4];
#pragma unroll
    for (int mi = 0; mi < 2; mi++)
#pragma unroll
        for (int j = 0; j < 8; j++)
#pragma unroll
            for (int r = 0; r < 4; r++) acc[mi][j][r] = 0.f;

    // ---- 4 K=64 chunks ----
    for (int c = 0; c < 4; c++) {
        if (c) __syncthreads();   // previous compute done before overwrite
        const float* Asrc = (c < 2) ? (const float*)g_hneigh : hself;
        int kk = (c & 1) * 64;
#pragma unroll
        for (int i = 0; i < 8; i++) {
            int f   = i * 256 + tid;        // 2048 float4
            int row = f >> 4;               // 0..127
            int kb  = (f & 15) << 2;        // 0..60
            int gr  = m0 + row;
            if (gr > n_dst - 1) gr = n_dst - 1;
            float4 v = *reinterpret_cast<const float4*>(
                Asrc + (size_t)gr * F_IN_C + kk + kb);
            int mblock = row >> 4, r8 = row & 7, half = (row >> 3) & 1;
            int kstep  = kb >> 3;
            int khalf  = (kb >> 2) & 1;
            uint32_t base = sb + SM_A + (uint32_t)((mblock * 8 + kstep) * AGRP) * 4u;
            uint32_t va[4] = { f2tf32(v.x), f2tf32(v.y), f2tf32(v.z), f2tf32(v.w) };
#pragma unroll
            for (int e = 0; e < 4; e++) {
                int l = (r8 << 2) | e;
                sts32(base + (uint32_t)(l * 4 + khalf * 2 + half) * 4u, va[e]);
            }
        }
        __syncthreads();

#pragma unroll
        for (int s = 0; s < 8; s++) {
            int sg = c * 8 + s;   // global k-step for B
            uint32_t bfrag[8][2];
#pragma unroll
            for (int j = 0; j < 8; j++) {
                int nblock = wn * 8 + j;
                lds64(bfrag[j],
                      sb + SM_B + (uint32_t)(((nblock * 32 + sg) * BGRP) + lane * 2) * 4u);
            }
#pragma unroll
            for (int mi = 0; mi < 2; mi++) {
                int mblock = wm * 2 + mi;
                uint32_t afrag[4];
                lds128(afrag,
                       sb + SM_A + (uint32_t)(((mblock * 8 + s) * AGRP) + lane * 4) * 4u);
#pragma unroll
                for (int j = 0; j < 8; j++)
                    mma_tf32(acc[mi][j], afrag, bfrag[j]);
            }
        }
    }

    // ---- epilogue: bias + store ----
    int colq = (lane & 3) * 2;        // col pair within 8-wide n-frag
    int rowq = lane >> 2;             // row within 8-wide half
#pragma unroll
    for (int mi = 0; mi < 2; mi++) {
        int r0 = m0 + wm * 32 + mi * 16 + rowq;
        int r1 = r0 + 8;
#pragma unroll
        for (int j = 0; j < 8; j++) {
            int col = wn * 64 + j * 8 + colq;
            float2 b2 = *reinterpret_cast<const float2*>(bias + col);
            if (r0 < n_dst) {
                float2 o = make_float2(acc[mi][j][0] + b2.x, acc[mi][j][1] + b2.y);
                *reinterpret_cast<float2*>(out + (size_t)r0 * F_OUT_C + col) = o;
            }
            if (r1 < n_dst) {
                float2 o = make_float2(acc[mi][j][2] + b2.x, acc[mi][j][3] + b2.y);
                *reinterpret_cast<float2*>(out + (size_t)r1 * F_OUT_C + col) = o;
            }
        }
    }
}

// ---------------------------------------------------------------------------
// Launch
// ---------------------------------------------------------------------------
extern "C" void kernel_launch(void* const* d_in, const int* in_sizes, int n_in,
                              void* d_out, int out_size) {
    const int*   codes    = (const int*)d_in[0];
    const int*   indices  = (const int*)d_in[1];
    const int*   indptr   = (const int*)d_in[2];
    const float* h_self   = (const float*)d_in[3];
    const float* codebook = (const float*)d_in[4];
    const float* Wn       = (const float*)d_in[5];
    const float* Ws       = (const float*)d_in[6];
    const float* b_self   = (const float*)d_in[7];
    float* out = (float*)d_out;

    int n_src = in_sizes[0] / P_C;
    int n_dst = in_sizes[2] - 1;

    {
        int total = n_src * 32;
        decode_kernel<<<(total + 255) / 256, 256>>>(codes, codebook, n_src);
    }
    {
        int total = n_dst * 32;
        gather_kernel<<<(total + 255) / 256, 256>>>(indices, indptr, n_dst);
    }
    {
        cudaFuncSetAttribute(gemm_mma_kernel,
                             cudaFuncAttributeMaxDynamicSharedMemorySize, SM_TOT);
        int blocks = (n_dst + 127) / 128;
        gemm_mma_kernel<<<blocks, 256, SM_TOT>>>(h_self, Wn, Ws, b_self, out, n_dst);
    }
}

// round 6
// speedup vs baseline: 1.9345x; 1.1666x over previous
#include <cuda_runtime.h>
#include <cstdint>
#include <cstddef>

#define P_C     16
#define W_C     8
#define F_IN_C  128
#define F_OUT_C 128
#define N_DST_MAX 100000

__device__ float g_hneigh[(size_t)N_DST_MAX * F_IN_C];

// ---------------------------------------------------------------------------
// Kernel 1 (fused decode+gather+mean): codebook lives in smem (128 KB).
// One warp per destination; lane l covers features [4l, 4l+4)
// (partition p = l>>1, w-offset = (l&1)*4). Per edge: one 4B code LDG
// (coalesced 64B across the warp) + one LDS.128 from the smem codebook.
// Grid: 148 CTAs x 1024 thr (1 CTA/SM, smem-limited), warp-stride dst loop.
// ---------------------------------------------------------------------------
#define GW_THREADS 1024
#define GW_BLOCKS  148

__global__ __launch_bounds__(GW_THREADS, 1) void gather_fused_kernel(
    const int* __restrict__ codes,
    const int* __restrict__ indices,
    const int* __restrict__ indptr,
    const float* __restrict__ codebook,
    int n_dst) {
    extern __shared__ float cb[];   // [16][256][8] = 32768 floats = 128 KB

    int tid  = threadIdx.x;
    int lane = tid & 31;
    int wid  = tid >> 5;

    // cooperative codebook load: 8192 float4 / 1024 thr = 8 per thread
#pragma unroll
    for (int i = 0; i < 8; i++) {
        int f4 = i * GW_THREADS + tid;
        float4 v = *reinterpret_cast<const float4*>(codebook + f4 * 4);
        *reinterpret_cast<float4*>(cb + f4 * 4) = v;
    }
    __syncthreads();

    int p  = lane >> 1;
    int w4 = (lane & 1) << 2;
    const float* cb_pw = cb + (p << 11) + w4;   // + code*8 per lookup

    int nwarps = GW_BLOCKS * (GW_THREADS / 32);
    for (int dst = blockIdx.x * (GW_THREADS / 32) + wid; dst < n_dst; dst += nwarps) {
        int start = __ldg(indptr + dst);
        int end   = __ldg(indptr + dst + 1);
        int deg   = end - start;

        float4 acc = make_float4(0.f, 0.f, 0.f, 0.f);

        if (deg == 16) {
            int my_idx = __ldg(indices + start + (lane & 15));
            int code[16];
#pragma unroll
            for (int e = 0; e < 16; e++) {
                int src = __shfl_sync(0xffffffffu, my_idx, e);
                code[e] = __ldg(codes + src * P_C + p);
            }
#pragma unroll
            for (int e = 0; e < 16; e++) {
                float4 v = *reinterpret_cast<const float4*>(cb_pw + (code[e] << 3));
                acc.x += v.x; acc.y += v.y; acc.z += v.z; acc.w += v.w;
            }
        } else {
            int my_idx = (lane < deg) ? __ldg(indices + start + lane) : 0;
            for (int e = 0; e < deg; e++) {
                int src = (e < 32) ? __shfl_sync(0xffffffffu, my_idx, e)
                                   : __ldg(indices + start + e);
                int c = __ldg(codes + src * P_C + p);
                float4 v = *reinterpret_cast<const float4*>(cb_pw + (c << 3));
                acc.x += v.x; acc.y += v.y; acc.z += v.z; acc.w += v.w;
            }
        }
        float s = 1.0f / fmaxf((float)deg, 1.0f);
        acc.x *= s; acc.y *= s; acc.z *= s; acc.w *= s;
        *reinterpret_cast<float4*>(g_hneigh + (size_t)dst * F_IN_C + (lane << 2)) = acc;
    }
}

// ---------------------------------------------------------------------------
// Kernel 2: tf32 mma.sync GEMM (unchanged from R5).
//   out[M,128] = [h_neigh | h_self] (M x 256) @ [Wn | Ws]^T (256 x 128) + bias
// ---------------------------------------------------------------------------
__device__ __forceinline__ uint32_t f2tf32(float x) {
    uint32_t r;
    asm("cvt.rna.tf32.f32 %0, %1;" : "=r"(r) : "f"(x));
    return r;
}
__device__ __forceinline__ uint32_t smem_u32(const void* p) {
    uint32_t a;
    asm("{ .reg .u64 t; cvta.to.shared.u64 t, %1; cvt.u32.u64 %0, t; }"
        : "=r"(a) : "l"(p));
    return a;
}
__device__ __forceinline__ void sts32(uint32_t addr, uint32_t v) {
    asm volatile("st.shared.b32 [%0], %1;" :: "r"(addr), "r"(v) : "memory");
}
__device__ __forceinline__ void lds128(uint32_t* r, uint32_t addr) {
    asm volatile("ld.shared.v4.b32 {%0,%1,%2,%3}, [%4];"
                 : "=r"(r[0]), "=r"(r[1]), "=r"(r[2]), "=r"(r[3]) : "r"(addr));
}
__device__ __forceinline__ void lds64(uint32_t* r, uint32_t addr) {
    asm volatile("ld.shared.v2.b32 {%0,%1}, [%2];"
                 : "=r"(r[0]), "=r"(r[1]) : "r"(addr));
}
__device__ __forceinline__ void mma_tf32(float* d, const uint32_t* a, const uint32_t* b) {
    asm volatile(
        "mma.sync.aligned.m16n8k8.row.col.f32.tf32.tf32.f32 "
        "{%0,%1,%2,%3}, {%4,%5,%6,%7}, {%8,%9}, {%0,%1,%2,%3};"
        : "+f"(d[0]), "+f"(d[1]), "+f"(d[2]), "+f"(d[3])
        : "r"(a[0]), "r"(a[1]), "r"(a[2]), "r"(a[3]), "r"(b[0]), "r"(b[1]));
}

#define BGRP   66
#define AGRP   132
#define SM_B   0
#define SM_A   (16 * 32 * BGRP * 4)       // 135168
#define SM_TOT (SM_A + 8 * 8 * AGRP * 4)  // 168960

__global__ __launch_bounds__(256, 1) void gemm_mma_kernel(
    const float* __restrict__ hself,
    const float* __restrict__ Wn,
    const float* __restrict__ Ws,
    const float* __restrict__ bias,
    float* __restrict__ out,
    int n_dst) {
    extern __shared__ char smem[];
    uint32_t sb = smem_u32(smem);
    int tid  = threadIdx.x;
    int wid  = tid >> 5;
    int lane = tid & 31;
    int m0   = blockIdx.x * 128;
    int wm   = wid & 3;
    int wn   = wid >> 2;

#pragma unroll
    for (int i = 0; i < 32; i++) {
        int f  = i * 256 + tid;
        int n  = f >> 6;
        int kb = (f & 63) << 2;
        const float* src = (kb < 128) ? (Wn + n * 128 + kb)
                                      : (Ws + n * 128 + (kb - 128));
        float4 v = *reinterpret_cast<const float4*>(src);
        int nblock = n >> 3, n8 = n & 7;
        int kstep  = kb >> 3;
        int reg    = (kb >> 2) & 1;
        uint32_t base = sb + SM_B + (uint32_t)((nblock * 32 + kstep) * BGRP) * 4u;
        uint32_t va[4] = { f2tf32(v.x), f2tf32(v.y), f2tf32(v.z), f2tf32(v.w) };
#pragma unroll
        for (int e = 0; e < 4; e++) {
            int l = (n8 << 2) | e;
            sts32(base + (uint32_t)(l * 2 + reg) * 4u, va[e]);
        }
    }

    float acc[2][8][4];
#pragma unroll
    for (int mi = 0; mi < 2; mi++)
#pragma unroll
        for (int j = 0; j < 8; j++)
#pragma unroll
            for (int r = 0; r < 4; r++) acc[mi][j][r] = 0.f;

    for (int c = 0; c < 4; c++) {
        if (c) __syncthreads();
        const float* Asrc = (c < 2) ? (const float*)g_hneigh : hself;
        int kk = (c & 1) * 64;
#pragma unroll
        for (int i = 0; i < 8; i++) {
            int f   = i * 256 + tid;
            int row = f >> 4;
            int kb  = (f & 15) << 2;
            int gr  = m0 + row;
            if (gr > n_dst - 1) gr = n_dst - 1;
            float4 v = *reinterpret_cast<const float4*>(
                Asrc + (size_t)gr * F_IN_C + kk + kb);
            int mblock = row >> 4, r8 = row & 7, half = (row >> 3) & 1;
            int kstep  = kb >> 3;
            int khalf  = (kb >> 2) & 1;
            uint32_t base = sb + SM_A + (uint32_t)((mblock * 8 + kstep) * AGRP) * 4u;
            uint32_t va[4] = { f2tf32(v.x), f2tf32(v.y), f2tf32(v.z), f2tf32(v.w) };
#pragma unroll
            for (int e = 0; e < 4; e++) {
                int l = (r8 << 2) | e;
                sts32(base + (uint32_t)(l * 4 + khalf * 2 + half) * 4u, va[e]);
            }
        }
        __syncthreads();

#pragma unroll
        for (int s = 0; s < 8; s++) {
            int sg = c * 8 + s;
            uint32_t bfrag[8][2];
#pragma unroll
            for (int j = 0; j < 8; j++) {
                int nblock = wn * 8 + j;
                lds64(bfrag[j],
                      sb + SM_B + (uint32_t)(((nblock * 32 + sg) * BGRP) + lane * 2) * 4u);
            }
#pragma unroll
            for (int mi = 0; mi < 2; mi++) {
                int mblock = wm * 2 + mi;
                uint32_t afrag[4];
                lds128(afrag,
                       sb + SM_A + (uint32_t)(((mblock * 8 + s) * AGRP) + lane * 4) * 4u);
#pragma unroll
                for (int j = 0; j < 8; j++)
                    mma_tf32(acc[mi][j], afrag, bfrag[j]);
            }
        }
    }

    int colq = (lane & 3) * 2;
    int rowq = lane >> 2;
#pragma unroll
    for (int mi = 0; mi < 2; mi++) {
        int r0 = m0 + wm * 32 + mi * 16 + rowq;
        int r1 = r0 + 8;
#pragma unroll
        for (int j = 0; j < 8; j++) {
            int col = wn * 64 + j * 8 + colq;
            float2 b2 = *reinterpret_cast<const float2*>(bias + col);
            if (r0 < n_dst) {
                float2 o = make_float2(acc[mi][j][0] + b2.x, acc[mi][j][1] + b2.y);
                *reinterpret_cast<float2*>(out + (size_t)r0 * F_OUT_C + col) = o;
            }
            if (r1 < n_dst) {
                float2 o = make_float2(acc[mi][j][2] + b2.x, acc[mi][j][3] + b2.y);
                *reinterpret_cast<float2*>(out + (size_t)r1 * F_OUT_C + col) = o;
            }
        }
    }
}

// ---------------------------------------------------------------------------
// Launch
// ---------------------------------------------------------------------------
extern "C" void kernel_launch(void* const* d_in, const int* in_sizes, int n_in,
                              void* d_out, int out_size) {
    const int*   codes    = (const int*)d_in[0];
    const int*   indices  = (const int*)d_in[1];
    const int*   indptr   = (const int*)d_in[2];
    const float* h_self   = (const float*)d_in[3];
    const float* codebook = (const float*)d_in[4];
    const float* Wn       = (const float*)d_in[5];
    const float* Ws       = (const float*)d_in[6];
    const float* b_self   = (const float*)d_in[7];
    float* out = (float*)d_out;

    int n_dst = in_sizes[2] - 1;

    {
        const int cb_bytes = P_C * 256 * W_C * 4;   // 131072
        cudaFuncSetAttribute(gather_fused_kernel,
                             cudaFuncAttributeMaxDynamicSharedMemorySize, cb_bytes);
        gather_fused_kernel<<<GW_BLOCKS, GW_THREADS, cb_bytes>>>(
            codes, indices, indptr, codebook, n_dst);
    }
    {
        cudaFuncSetAttribute(gemm_mma_kernel,
                             cudaFuncAttributeMaxDynamicSharedMemorySize, SM_TOT);
        int blocks = (n_dst + 127) / 128;
        gemm_mma_kernel<<<blocks, 256, SM_TOT>>>(h_self, Wn, Ws, b_self, out, n_dst);
    }
}

// round 7
// speedup vs baseline: 2.4636x; 1.2736x over previous
#include <cuda_runtime.h>
#include <cuda_fp16.h>
#include <cstdint>
#include <cstddef>

#define P_C     16
#define W_C     8
#define F_IN_C  128
#define F_OUT_C 128
#define N_DST_MAX 100000

__device__ float g_hneigh[(size_t)N_DST_MAX * F_IN_C];

// ---------------------------------------------------------------------------
// Kernel 1 (fused decode+gather+mean), fp16 codebook in smem (64 KB).
// Entry (p,code) = 8 halfs = 16 B = one LDS.128.
// Fast path (deg==16): lane = (h, p) with p = lane&15, h = lane>>4.
// Each step s handles edge pair (2s, 2s+1): lane reads the FULL entry of
// partition p for edge 2s+h, accumulates 4 half2. Final cross-half combine
// in fp32 via shfl. 8 steps per dst instead of 16.
// ---------------------------------------------------------------------------
#define GW_THREADS 512
#define GW_BLOCKS  444

__global__ __launch_bounds__(GW_THREADS, 3) void gather_fused_kernel(
    const int* __restrict__ codes,
    const int* __restrict__ indices,
    const int* __restrict__ indptr,
    const float* __restrict__ codebook,
    int n_dst) {
    extern __shared__ __half2 cbh[];   // 16 KB half2 = 64 KB (16x256 entries)

    int tid  = threadIdx.x;
    int lane = tid & 31;
    int wid  = tid >> 5;

    // cooperative load+convert: 32768 floats -> 16384 half2; 8 floats/thread/iter
#pragma unroll
    for (int i = 0; i < 8; i++) {
        int blk = i * GW_THREADS + tid;          // 0..4095
        const float4* s = reinterpret_cast<const float4*>(codebook + blk * 8);
        float4 a = __ldg(s);
        float4 b = __ldg(s + 1);
        __half2 h0 = __floats2half2_rn(a.x, a.y);
        __half2 h1 = __floats2half2_rn(a.z, a.w);
        __half2 h2 = __floats2half2_rn(b.x, b.y);
        __half2 h3 = __floats2half2_rn(b.z, b.w);
        uint4 pk;
        pk.x = *reinterpret_cast<uint32_t*>(&h0);
        pk.y = *reinterpret_cast<uint32_t*>(&h1);
        pk.z = *reinterpret_cast<uint32_t*>(&h2);
        pk.w = *reinterpret_cast<uint32_t*>(&h3);
        reinterpret_cast<uint4*>(cbh)[blk] = pk;
    }
    __syncthreads();

    int p = lane & 15;
    int h = lane >> 4;
    const __half2* cb_p = cbh + (p << 10);   // p * 1024 half2 (= p*2048 halfs)

    int nwarps = GW_BLOCKS * (GW_THREADS / 32);
    for (int dst = blockIdx.x * (GW_THREADS / 32) + wid; dst < n_dst; dst += nwarps) {
        int start = __ldg(indptr + dst);
        int deg   = __ldg(indptr + dst + 1) - start;

        if (deg == 16) {
            int my_idx = __ldg(indices + start + (lane & 15));
            int c[8];
#pragma unroll
            for (int s = 0; s < 8; s++) {
                int src = __shfl_sync(0xffffffffu, my_idx, 2 * s + h);
                c[s] = __ldg(codes + src * P_C + p);
            }
            __half2 acc0 = __float2half2_rn(0.f), acc1 = acc0, acc2 = acc0, acc3 = acc0;
#pragma unroll
            for (int s = 0; s < 8; s++) {
                uint4 v = *reinterpret_cast<const uint4*>(cb_p + c[s] * 4);
                acc0 = __hadd2(acc0, *reinterpret_cast<__half2*>(&v.x));
                acc1 = __hadd2(acc1, *reinterpret_cast<__half2*>(&v.y));
                acc2 = __hadd2(acc2, *reinterpret_cast<__half2*>(&v.z));
                acc3 = __hadd2(acc3, *reinterpret_cast<__half2*>(&v.w));
            }
            // combine h=0/h=1 partials in fp32 (lanes 0-15 write)
            uint32_t u0 = *reinterpret_cast<uint32_t*>(&acc0);
            uint32_t u1 = *reinterpret_cast<uint32_t*>(&acc1);
            uint32_t u2 = *reinterpret_cast<uint32_t*>(&acc2);
            uint32_t u3 = *reinterpret_cast<uint32_t*>(&acc3);
            uint32_t q0 = __shfl_down_sync(0xffffffffu, u0, 16);
            uint32_t q1 = __shfl_down_sync(0xffffffffu, u1, 16);
            uint32_t q2 = __shfl_down_sync(0xffffffffu, u2, 16);
            uint32_t q3 = __shfl_down_sync(0xffffffffu, u3, 16);
            if (lane < 16) {
                float2 f0 = __half22float2(*reinterpret_cast<__half2*>(&u0));
                float2 f1 = __half22float2(*reinterpret_cast<__half2*>(&u1));
                float2 f2 = __half22float2(*reinterpret_cast<__half2*>(&u2));
                float2 f3 = __half22float2(*reinterpret_cast<__half2*>(&u3));
                float2 g0 = __half22float2(*reinterpret_cast<__half2*>(&q0));
                float2 g1 = __half22float2(*reinterpret_cast<__half2*>(&q1));
                float2 g2 = __half22float2(*reinterpret_cast<__half2*>(&q2));
                float2 g3 = __half22float2(*reinterpret_cast<__half2*>(&q3));
                const float s16 = 1.0f / 16.0f;
                float4 o0 = make_float4((f0.x + g0.x) * s16, (f0.y + g0.y) * s16,
                                        (f1.x + g1.x) * s16, (f1.y + g1.y) * s16);
                float4 o1 = make_float4((f2.x + g2.x) * s16, (f2.y + g2.y) * s16,
                                        (f3.x + g3.x) * s16, (f3.y + g3.y) * s16);
                float* dstp = g_hneigh + (size_t)dst * F_IN_C + p * 8;
                *reinterpret_cast<float4*>(dstp)     = o0;
                *reinterpret_cast<float4*>(dstp + 4) = o1;
            }
        } else {
            // generic fallback: lane covers features p*8 + h*4 .. +4
            float4 acc = make_float4(0.f, 0.f, 0.f, 0.f);
            for (int e = 0; e < deg; e++) {
                int src = __ldg(indices + start + e);
                int c = __ldg(codes + src * P_C + p);
                __half2 a = cb_p[c * 4 + h * 2];
                __half2 b = cb_p[c * 4 + h * 2 + 1];
                float2 fa = __half22float2(a), fb = __half22float2(b);
                acc.x += fa.x; acc.y += fa.y; acc.z += fb.x; acc.w += fb.y;
            }
            float s = 1.0f / fmaxf((float)deg, 1.0f);
            acc.x *= s; acc.y *= s; acc.z *= s; acc.w *= s;
            *reinterpret_cast<float4*>(
                g_hneigh + (size_t)dst * F_IN_C + p * 8 + h * 4) = acc;
        }
    }
}

// ---------------------------------------------------------------------------
// Kernel 2: persistent tf32 mma.sync GEMM, 512 thr (16 warps, 4x4 warp grid,
// warp tile 32x32). B staged once per CTA; A double-buffered per K=64 chunk
// with load-regs -> MMA -> store-smem pipelining.
// ---------------------------------------------------------------------------
__device__ __forceinline__ uint32_t f2tf32(float x) {
    uint32_t r;
    asm("cvt.rna.tf32.f32 %0, %1;" : "=r"(r) : "f"(x));
    return r;
}
__device__ __forceinline__ uint32_t smem_u32(const void* p) {
    uint32_t a;
    asm("{ .reg .u64 t; cvta.to.shared.u64 t, %1; cvt.u32.u64 %0, t; }"
        : "=r"(a) : "l"(p));
    return a;
}
__device__ __forceinline__ void sts32(uint32_t addr, uint32_t v) {
    asm volatile("st.shared.b32 [%0], %1;" :: "r"(addr), "r"(v) : "memory");
}
__device__ __forceinline__ void lds128(uint32_t* r, uint32_t addr) {
    asm volatile("ld.shared.v4.b32 {%0,%1,%2,%3}, [%4];"
                 : "=r"(r[0]), "=r"(r[1]), "=r"(r[2]), "=r"(r[3]) : "r"(addr));
}
__device__ __forceinline__ void lds64(uint32_t* r, uint32_t addr) {
    asm volatile("ld.shared.v2.b32 {%0,%1}, [%2];"
                 : "=r"(r[0]), "=r"(r[1]) : "r"(addr));
}
__device__ __forceinline__ void mma_tf32(float* d, const uint32_t* a, const uint32_t* b) {
    asm volatile(
        "mma.sync.aligned.m16n8k8.row.col.f32.tf32.tf32.f32 "
        "{%0,%1,%2,%3}, {%4,%5,%6,%7}, {%8,%9}, {%0,%1,%2,%3};"
        : "+f"(d[0]), "+f"(d[1]), "+f"(d[2]), "+f"(d[3])
        : "r"(a[0]), "r"(a[1]), "r"(a[2]), "r"(a[3]), "r"(b[0]), "r"(b[1]));
}

#define GEMM_THREADS 512
#define BGRP   66
#define AGRP   132
#define SM_B   0
#define SM_A0  (16 * 32 * BGRP * 4)            // 135168
#define SM_A1  (SM_A0 + 8 * 8 * AGRP * 4)      // 168960
#define SM_TOT (SM_A1 + 8 * 8 * AGRP * 4)      // 202752

__global__ __launch_bounds__(GEMM_THREADS, 1) void gemm_mma_kernel(
    const float* __restrict__ hneigh,
    const float* __restrict__ hself,
    const float* __restrict__ Wn,
    const float* __restrict__ Ws,
    const float* __restrict__ bias,
    float* __restrict__ out,
    int n_dst) {
    extern __shared__ char smem[];
    uint32_t sb = smem_u32(smem);
    int tid  = threadIdx.x;
    int wid  = tid >> 5;
    int lane = tid & 31;
    int wm   = wid >> 2;   // 0..3: rows wm*32..+31
    int wn   = wid & 3;    // 0..3: cols wn*32..+31

    // ---- stage B once (128 x 256 -> permuted tf32 fragments) ----
#pragma unroll
    for (int i = 0; i < 16; i++) {
        int f  = i * GEMM_THREADS + tid;   // 8192 float4
        int n  = f >> 6;
        int kb = (f & 63) << 2;
        const float* src = (kb < 128) ? (Wn + n * 128 + kb)
                                      : (Ws + n * 128 + (kb - 128));
        float4 v = *reinterpret_cast<const float4*>(src);
        int nblock = n >> 3, n8 = n & 7;
        int kstep  = kb >> 3;
        int reg    = (kb >> 2) & 1;
        uint32_t base = sb + SM_B + (uint32_t)((nblock * 32 + kstep) * BGRP) * 4u;
        uint32_t va[4] = { f2tf32(v.x), f2tf32(v.y), f2tf32(v.z), f2tf32(v.w) };
#pragma unroll
        for (int e = 0; e < 4; e++) {
            int l = (n8 << 2) | e;
            sts32(base + (uint32_t)(l * 2 + reg) * 4u, va[e]);
        }
    }

    // bias per warp (fixed cols)
    float bj[2][4][2];   // [colq half ignored] -> store per j: 2 floats at colq
    int colq = (lane & 3) * 2;
    int rowq = lane >> 2;
#pragma unroll
    for (int j = 0; j < 4; j++) {
        float2 b2 = *reinterpret_cast<const float2*>(bias + wn * 32 + j * 8 + colq);
        bj[0][j][0] = b2.x; bj[0][j][1] = b2.y;
    }

    int ntiles = (n_dst + 127) >> 7;

    for (int tile = blockIdx.x; tile < ntiles; tile += gridDim.x) {
        int m0 = tile << 7;

        float acc[2][4][4];
#pragma unroll
        for (int mi = 0; mi < 2; mi++)
#pragma unroll
            for (int j = 0; j < 4; j++)
#pragma unroll
                for (int r = 0; r < 4; r++) acc[mi][j][r] = 0.f;

        // ---- software-pipelined chunks: load c+1 regs, MMA c, store c+1 ----
        float4 vreg[4];
        int rowr[4];
        // prologue: load + store chunk 0 into buf0
#pragma unroll
        for (int i = 0; i < 4; i++) {
            int f   = i * GEMM_THREADS + tid;
            int row = f >> 4;
            int kb  = (f & 15) << 2;
            int gr  = m0 + row;
            if (gr > n_dst - 1) gr = n_dst - 1;
            vreg[i] = *reinterpret_cast<const float4*>(
                hneigh + (size_t)gr * F_IN_C + kb);
            rowr[i] = row;
        }
#pragma unroll
        for (int i = 0; i < 4; i++) {
            int f   = i * GEMM_THREADS + tid;
            int row = rowr[i];
            int kb  = (f & 15) << 2;
            int mblock = row >> 4, r8 = row & 7, half = (row >> 3) & 1;
            int kstep  = kb >> 3;
            int khalf  = (kb >> 2) & 1;
            uint32_t base = sb + SM_A0 + (uint32_t)((mblock * 8 + kstep) * AGRP) * 4u;
            uint32_t va[4] = { f2tf32(vreg[i].x), f2tf32(vreg[i].y),
                               f2tf32(vreg[i].z), f2tf32(vreg[i].w) };
#pragma unroll
            for (int e = 0; e < 4; e++) {
                int l = (r8 << 2) | e;
                sts32(base + (uint32_t)(l * 4 + khalf * 2 + half) * 4u, va[e]);
            }
        }
        __syncthreads();

#pragma unroll
        for (int c = 0; c < 4; c++) {
            // load regs for chunk c+1
            if (c < 3) {
                const float* Asrc = (c + 1 < 2) ? hneigh : hself;
                int kk = ((c + 1) & 1) * 64;
#pragma unroll
                for (int i = 0; i < 4; i++) {
                    int f   = i * GEMM_THREADS + tid;
                    int row = f >> 4;
                    int kb  = (f & 15) << 2;
                    int gr  = m0 + row;
                    if (gr > n_dst - 1) gr = n_dst - 1;
                    vreg[i] = *reinterpret_cast<const float4*>(
                        Asrc + (size_t)gr * F_IN_C + kk + kb);
                }
            }

            // MMA on chunk c (buffer c&1)
            uint32_t abase = sb + ((c & 1) ? SM_A1 : SM_A0);
#pragma unroll
            for (int s = 0; s < 8; s++) {
                int sg = c * 8 + s;
                uint32_t bfrag[4][2];
#pragma unroll
                for (int j = 0; j < 4; j++) {
                    int nblock = wn * 4 + j;
                    lds64(bfrag[j],
                          sb + SM_B + (uint32_t)(((nblock * 32 + sg) * BGRP) + lane * 2) * 4u);
                }
#pragma unroll
                for (int mi = 0; mi < 2; mi++) {
                    int mblock = wm * 2 + mi;
                    uint32_t afrag[4];
                    lds128(afrag,
                           abase + (uint32_t)(((mblock * 8 + s) * AGRP) + lane * 4) * 4u);
#pragma unroll
                    for (int j = 0; j < 4; j++)
                        mma_tf32(acc[mi][j], afrag, bfrag[j]);
                }
            }

            // store chunk c+1 to the other buffer
            if (c < 3) {
                uint32_t nbase = sb + (((c + 1) & 1) ? SM_A1 : SM_A0);
#pragma unroll
                for (int i = 0; i < 4; i++) {
                    int f   = i * GEMM_THREADS + tid;
                    int row = f >> 4;
                    int kb  = (f & 15) << 2;
                    int mblock = row >> 4, r8 = row & 7, half = (row >> 3) & 1;
                    int kstep  = kb >> 3;
                    int khalf  = (kb >> 2) & 1;
                    uint32_t base = nbase + (uint32_t)((mblock * 8 + kstep) * AGRP) * 4u;
                    uint32_t va[4] = { f2tf32(vreg[i].x), f2tf32(vreg[i].y),
                                       f2tf32(vreg[i].z), f2tf32(vreg[i].w) };
#pragma unroll
                    for (int e = 0; e < 4; e++) {
                        int l = (r8 << 2) | e;
                        sts32(base + (uint32_t)(l * 4 + khalf * 2 + half) * 4u, va[e]);
                    }
                }
            }
            __syncthreads();
        }

        // ---- epilogue ----
#pragma unroll
        for (int mi = 0; mi < 2; mi++) {
            int r0 = m0 + wm * 32 + mi * 16 + rowq;
            int r1 = r0 + 8;
#pragma unroll
            for (int j = 0; j < 4; j++) {
                int col = wn * 32 + j * 8 + colq;
                if (r0 < n_dst) {
                    float2 o = make_float2(acc[mi][j][0] + bj[0][j][0],
                                           acc[mi][j][1] + bj[0][j][1]);
                    *reinterpret_cast<float2*>(out + (size_t)r0 * F_OUT_C + col) = o;
                }
                if (r1 < n_dst) {
                    float2 o = make_float2(acc[mi][j][2] + bj[0][j][0],
                                           acc[mi][j][3] + bj[0][j][1]);
                    *reinterpret_cast<float2*>(out + (size_t)r1 * F_OUT_C + col) = o;
                }
            }
        }
    }
}

// ---------------------------------------------------------------------------
// Launch
// ---------------------------------------------------------------------------
extern "C" void kernel_launch(void* const* d_in, const int* in_sizes, int n_in,
                              void* d_out, int out_size) {
    const int*   codes    = (const int*)d_in[0];
    const int*   indices  = (const int*)d_in[1];
    const int*   indptr   = (const int*)d_in[2];
    const float* h_self   = (const float*)d_in[3];
    const float* codebook = (const float*)d_in[4];
    const float* Wn       = (const float*)d_in[5];
    const float* Ws       = (const float*)d_in[6];
    const float* b_self   = (const float*)d_in[7];
    float* out = (float*)d_out;

    int n_dst = in_sizes[2] - 1;

    {
        const int cb_bytes = P_C * 256 * W_C * 2;   // 65536 (fp16)
        cudaFuncSetAttribute(gather_fused_kernel,
                             cudaFuncAttributeMaxDynamicSharedMemorySize, cb_bytes);
        gather_fused_kernel<<<GW_BLOCKS, GW_THREADS, cb_bytes>>>(
            codes, indices, indptr, codebook, n_dst);
    }
    {
        cudaFuncSetAttribute(gemm_mma_kernel,
                             cudaFuncAttributeMaxDynamicSharedMemorySize, SM_TOT);
        float* hneigh;
        cudaGetSymbolAddress((void**)&hneigh, g_hneigh);
        gemm_mma_kernel<<<148, GEMM_THREADS, SM_TOT>>>(
            hneigh, h_self, Wn, Ws, b_self, out, n_dst);
    }
}